// round 3
// baseline (speedup 1.0000x reference)
#include <cuda_runtime.h>

// Problem constants (match reference_code)
#define NU    30000
#define NENT  70000
#define NN    100000          // NU + NENT
#define NEDGE 1600000
#define NB    4096

#define SCAN_T  512
#define NBLK    ((NN + SCAN_T - 1) / SCAN_T)   // 196

// Scratch (device globals: allocation-free rule).
__device__ float g_feats0[NN * 64];
__device__ float g_a1[NN * 64];
__device__ float g_a2[NN * 32];
// CSR scratch
__device__ int   g_cnt[NN];
__device__ int   g_rowptr[NN + 1];
__device__ int   g_cursor[NN];
__device__ int   g_part[NBLK];       // decoupled-lookback state, zeroed per launch
__device__ int2  g_ecv[NEDGE];       // x = col, y = float bits of val

// ---- f32x2 packed FMA helpers -------------------------------------------
__device__ __forceinline__ unsigned long long pack2(float lo, float hi) {
    unsigned long long r;
    asm("mov.b64 %0, {%1, %2};" : "=l"(r) : "f"(lo), "f"(hi));
    return r;
}
__device__ __forceinline__ void unpack2(unsigned long long v, float& lo, float& hi) {
    asm("mov.b64 {%0, %1}, %2;" : "=f"(lo), "=f"(hi) : "l"(v));
}
#define FMA2(d, a, b, c) \
    asm("fma.rn.f32x2 %0, %1, %2, %3;" : "=l"(d) : "l"(a), "l"(b), "l"(c))

// ---------------------------------------------------------------------------
// K0: zero CSR counters + lookback state
// ---------------------------------------------------------------------------
__global__ __launch_bounds__(256) void zero_kernel()
{
    int i = blockIdx.x * 256 + threadIdx.x;
    if (i < NN) g_cnt[i] = 0;
    if (i < NBLK) g_part[i] = 0;
}

// ---------------------------------------------------------------------------
// K1: a0 = concat(user_embed, entity_embed)
// ---------------------------------------------------------------------------
__global__ __launch_bounds__(256) void concat_kernel(
    const float* __restrict__ ue, const float* __restrict__ ee)
{
    int idx = blockIdx.x * 256 + threadIdx.x;           // over NN*16 float4
    if (idx >= NN * 16) return;
    float4 v = (idx < NU * 16) ? ((const float4*)ue)[idx]
                               : ((const float4*)ee)[idx - NU * 16];
    ((float4*)g_feats0)[idx] = v;
}

// ---------------------------------------------------------------------------
// K2: histogram of rows
// ---------------------------------------------------------------------------
__global__ __launch_bounds__(256) void hist_kernel(const int* __restrict__ er)
{
    int e = blockIdx.x * 256 + threadIdx.x;
    if (e < NEDGE) atomicAdd(&g_cnt[er[e]], 1);
}

// ---------------------------------------------------------------------------
// K3: single-pass exclusive scan (decoupled lookback). All NBLK=196 blocks
// are resident in one wave (4 blocks/SM x 148 SMs), so lookback cannot
// deadlock. Deterministic result.
// ---------------------------------------------------------------------------
__global__ __launch_bounds__(SCAN_T) void scan_kernel()
{
    __shared__ int wsum[16];
    __shared__ int sh_prefix;
    const int tid  = threadIdx.x;
    const int lane = tid & 31;
    const int wp   = tid >> 5;
    const int b    = blockIdx.x;
    const int i    = b * SCAN_T + tid;

    int v = (i < NN) ? g_cnt[i] : 0;
    int s = v;
    #pragma unroll
    for (int off = 1; off < 32; off <<= 1) {
        int t = __shfl_up_sync(0xFFFFFFFFu, s, off);
        if (lane >= off) s += t;
    }
    if (lane == 31) wsum[wp] = s;
    __syncthreads();
    if (wp == 0) {
        int ws = (lane < 16) ? wsum[lane] : 0;
        #pragma unroll
        for (int off = 1; off < 16; off <<= 1) {
            int t = __shfl_up_sync(0xFFFFFFFFu, ws, off);
            if (lane >= off) ws += t;
        }
        if (lane < 16) wsum[lane] = ws;           // inclusive warp sums
    }
    __syncthreads();
    int base  = (wp > 0) ? wsum[wp - 1] : 0;
    int incl  = base + s;                         // inclusive within block
    int total = wsum[15];

    if (tid == 0) {
        if (b == 0) {
            atomicExch(&g_part[0], (2 << 28) | total);
            sh_prefix = 0;
        } else {
            atomicExch(&g_part[b], (1 << 28) | total);
            int run = 0, j = b - 1;
            while (true) {
                int p = atomicAdd(&g_part[j], 0);
                int st = p >> 28;
                if (st == 0) continue;
                run += p & 0x0FFFFFFF;
                if (st == 2) break;
                j--;
            }
            atomicExch(&g_part[b], (2 << 28) | (run + total));
            sh_prefix = run;
        }
    }
    __syncthreads();
    int rp = sh_prefix + incl - v;                // exclusive global prefix
    if (i < NN) { g_rowptr[i] = rp; g_cursor[i] = rp; }
    if (i == NN) g_rowptr[NN] = NEDGE;
}

// ---------------------------------------------------------------------------
// K4: fill CSR adjacency (col, val) packed
// ---------------------------------------------------------------------------
__global__ __launch_bounds__(256) void fill_kernel(
    const int* __restrict__ er, const int* __restrict__ ec,
    const float* __restrict__ ev)
{
    int e = blockIdx.x * 256 + threadIdx.x;
    if (e >= NEDGE) return;
    int row = er[e];
    int pos = atomicAdd(&g_cursor[row], 1);
    g_ecv[pos] = make_int2(ec[e], __float_as_int(ev[e]));
}

// ---------------------------------------------------------------------------
// Fused layer: pull-mode gather -> shared Xs/Ys (k-major, pad 66) ->
// f32x2 GEMM -> leaky_relu -> L2 normalize.
// Block = 64 rows, 256 threads. Gather: warp per row, 2 edges in parallel
// (half-warp each, float4 per lane), shfl_xor(16) combine.
// GEMM: acc packed over node pairs; W staged dup-packed (w,w) in shared.
// ---------------------------------------------------------------------------
#define XPAD 66
template<int DOUT, int LAYER>
__global__ __launch_bounds__(256) void layer_fused_kernel(
    const float* __restrict__ W1, const float* __restrict__ b1,
    const float* __restrict__ W2, const float* __restrict__ b2)
{
    const float* __restrict__ feats = (LAYER == 0) ? g_feats0 : g_a1;
    float*       out                = (LAYER == 0) ? g_a1     : g_a2;

    extern __shared__ float sm[];
    float*  Xs  = sm;                           // [64 k][XPAD]
    float*  Ys  = Xs + 64 * XPAD;               // [64 k][XPAD]
    float2* W1d = (float2*)(Ys + 64 * XPAD);    // [64 k][DOUT] dup pairs
    float2* W2d = W1d + 64 * DOUT;
    float*  Bs  = (float*)(W2d + 64 * DOUT);    // [DOUT]

    const int tid  = threadIdx.x;
    const int r0   = blockIdx.x * 64;
    const int warp = tid >> 5;
    const int lane = tid & 31;
    const int c4   = lane & 15;                 // float4 index within row
    const int eo   = lane >> 4;                 // edge parity (half-warp)

    // ---- stage W dup-packed, bias sum ----
    for (int idx = tid; idx < 64 * DOUT; idx += 256) {
        float w1 = W1[idx], w2 = W2[idx];
        W1d[idx] = make_float2(w1, w1);
        W2d[idx] = make_float2(w2, w2);
    }
    if (tid < DOUT) Bs[tid] = b1[tid] + b2[tid];

    // ---- pull gather: 2 edges concurrently per warp ----
    #pragma unroll 1
    for (int i = 0; i < 8; i++) {
        int rl = warp * 8 + i;
        int gr = r0 + rl;
        float4 f = make_float4(0.f, 0.f, 0.f, 0.f);
        float4 h = f;
        if (gr < NN) {
            f = ((const float4*)feats)[gr * 16 + c4];
            int beg = g_rowptr[gr];
            int end = g_rowptr[gr + 1];
            #pragma unroll 2
            for (int e = beg + eo; e < end; e += 2) {
                int2 cv = g_ecv[e];
                float v = __int_as_float(cv.y);
                float4 g = ((const float4*)feats)[(size_t)cv.x * 16 + c4];
                h.x += g.x * v; h.y += g.y * v;
                h.z += g.z * v; h.w += g.w * v;
            }
        }
        h.x += __shfl_xor_sync(0xFFFFFFFFu, h.x, 16);
        h.y += __shfl_xor_sync(0xFFFFFFFFu, h.y, 16);
        h.z += __shfl_xor_sync(0xFFFFFFFFu, h.z, 16);
        h.w += __shfl_xor_sync(0xFFFFFFFFu, h.w, 16);
        int cb = c4 * 4;
        if (eo == 0) {                           // half 0 writes X
            Xs[(cb + 0) * XPAD + rl] = f.x + h.x;
            Xs[(cb + 1) * XPAD + rl] = f.y + h.y;
            Xs[(cb + 2) * XPAD + rl] = f.z + h.z;
            Xs[(cb + 3) * XPAD + rl] = f.w + h.w;
        } else {                                 // half 1 writes Y
            Ys[(cb + 0) * XPAD + rl] = f.x * h.x;
            Ys[(cb + 1) * XPAD + rl] = f.y * h.y;
            Ys[(cb + 2) * XPAD + rl] = f.z * h.z;
            Ys[(cb + 3) * XPAD + rl] = f.w * h.w;
        }
    }
    __syncthreads();

    // ---- f32x2 GEMM: thread (tx,ty) -> nodes ty*4..+3 (2 pairs) x JT outs
    constexpr int JT = DOUT / 16;               // 4 (layer0) or 2 (layer1)
    const int tx = tid & 15;
    const int ty = tid >> 4;

    unsigned long long acc[2][JT];
    #pragma unroll
    for (int j = 0; j < JT; j++) {
        unsigned long long bb = pack2(Bs[tx * JT + j], Bs[tx * JT + j]);
        acc[0][j] = bb;
        acc[1][j] = bb;
    }

    #pragma unroll 4
    for (int k = 0; k < 64; k++) {
        unsigned long long x0 = *(const unsigned long long*)&Xs[k * XPAD + ty * 4];
        unsigned long long x1 = *(const unsigned long long*)&Xs[k * XPAD + ty * 4 + 2];
        unsigned long long y0 = *(const unsigned long long*)&Ys[k * XPAD + ty * 4];
        unsigned long long y1 = *(const unsigned long long*)&Ys[k * XPAD + ty * 4 + 2];
        #pragma unroll
        for (int j = 0; j < JT; j++) {
            unsigned long long w1 = *(const unsigned long long*)&W1d[k * DOUT + tx * JT + j];
            unsigned long long w2 = *(const unsigned long long*)&W2d[k * DOUT + tx * JT + j];
            FMA2(acc[0][j], x0, w1, acc[0][j]);
            FMA2(acc[1][j], x1, w1, acc[1][j]);
            FMA2(acc[0][j], y0, w2, acc[0][j]);
            FMA2(acc[1][j], y1, w2, acc[1][j]);
        }
    }

    // ---- epilogue: leaky_relu + L2 normalize ----
    float val[4][JT];                            // [node in group][j]
    float p[4] = {0.f, 0.f, 0.f, 0.f};
    #pragma unroll
    for (int i2 = 0; i2 < 2; i2++)
        #pragma unroll
        for (int j = 0; j < JT; j++) {
            float lo, hi;
            unpack2(acc[i2][j], lo, hi);
            lo = (lo > 0.f) ? lo : 0.01f * lo;
            hi = (hi > 0.f) ? hi : 0.01f * hi;
            val[2 * i2 + 0][j] = lo;
            val[2 * i2 + 1][j] = hi;
            p[2 * i2 + 0] += lo * lo;
            p[2 * i2 + 1] += hi * hi;
        }
    #pragma unroll
    for (int i = 0; i < 4; i++) {
        float q = p[i];
        q += __shfl_xor_sync(0xFFFFFFFFu, q, 1, 16);
        q += __shfl_xor_sync(0xFFFFFFFFu, q, 2, 16);
        q += __shfl_xor_sync(0xFFFFFFFFu, q, 4, 16);
        q += __shfl_xor_sync(0xFFFFFFFFu, q, 8, 16);
        float inv = 1.f / fmaxf(sqrtf(q), 1e-12f);
        int gr = r0 + ty * 4 + i;
        if (gr < NN) {
            if constexpr (JT == 4) {
                float4 o = make_float4(val[i][0] * inv, val[i][1] * inv,
                                       val[i][2] * inv, val[i][3] * inv);
                ((float4*)out)[gr * (DOUT / 4) + tx] = o;
            } else {
                float2 o = make_float2(val[i][0] * inv, val[i][1] * inv);
                ((float2*)out)[gr * (DOUT / 2) + tx] = o;
            }
        }
    }
}

// ---------------------------------------------------------------------------
// Scoring — warp per pair, dot over concat(a0[64], a1[64], a2[32]).
// ---------------------------------------------------------------------------
__global__ __launch_bounds__(256) void score_kernel(
    const int* __restrict__ uids, const int* __restrict__ iids,
    float* __restrict__ out)
{
    int w = (blockIdx.x * 256 + threadIdx.x) >> 5;
    int l = threadIdx.x & 31;
    if (w >= NB) return;
    int u  = uids[w];
    int it = NU + iids[w];

    const float* fu = g_feats0 + u  * 64;
    const float* fi = g_feats0 + it * 64;
    float s = fu[l] * fi[l] + fu[l + 32] * fi[l + 32];
    const float* au = g_a1 + u  * 64;
    const float* ai = g_a1 + it * 64;
    s += au[l] * ai[l] + au[l + 32] * ai[l + 32];
    s += g_a2[u * 32 + l] * g_a2[it * 32 + l];

    s += __shfl_xor_sync(0xFFFFFFFFu, s, 16);
    s += __shfl_xor_sync(0xFFFFFFFFu, s, 8);
    s += __shfl_xor_sync(0xFFFFFFFFu, s, 4);
    s += __shfl_xor_sync(0xFFFFFFFFu, s, 2);
    s += __shfl_xor_sync(0xFFFFFFFFu, s, 1);
    if (l == 0) out[w] = s;
}

// ---------------------------------------------------------------------------
extern "C" void kernel_launch(void* const* d_in, const int* in_sizes, int n_in,
                              void* d_out, int out_size)
{
    const int*   er   = (const int*)  d_in[0];
    const int*   ec   = (const int*)  d_in[1];
    const float* ev   = (const float*)d_in[2];
    const float* ue   = (const float*)d_in[3];
    const float* ee   = (const float*)d_in[4];
    const float* W1_0 = (const float*)d_in[5];
    const float* b1_0 = (const float*)d_in[6];
    const float* W2_0 = (const float*)d_in[7];
    const float* b2_0 = (const float*)d_in[8];
    const float* W1_1 = (const float*)d_in[9];
    const float* b1_1 = (const float*)d_in[10];
    const float* W2_1 = (const float*)d_in[11];
    const float* b2_1 = (const float*)d_in[12];
    const int*   uids = (const int*)  d_in[13];
    const int*   iids = (const int*)  d_in[14];
    float*       out  = (float*)d_out;

    const size_t smem64 = (size_t)(64 * XPAD * 2 + 64) * sizeof(float)
                        + (size_t)(64 * 64 * 2) * sizeof(float2);   // ~99.6 KB
    const size_t smem32 = (size_t)(64 * XPAD * 2 + 32) * sizeof(float)
                        + (size_t)(64 * 32 * 2) * sizeof(float2);   // ~66.2 KB
    cudaFuncSetAttribute(layer_fused_kernel<64, 0>,
                         cudaFuncAttributeMaxDynamicSharedMemorySize, (int)smem64);
    cudaFuncSetAttribute(layer_fused_kernel<32, 1>,
                         cudaFuncAttributeMaxDynamicSharedMemorySize, (int)smem32);

    const int layer_blocks = (NN + 63) / 64;
    const int eblocks = (NEDGE + 255) / 256;
    const int nblocks = (NN + 255) / 256;

    zero_kernel<<<nblocks, 256>>>();                                   // 0
    concat_kernel<<<(NN * 16 + 255) / 256, 256>>>(ue, ee);             // 1
    hist_kernel<<<eblocks, 256>>>(er);                                 // 2
    scan_kernel<<<NBLK, SCAN_T>>>();                                   // 3
    fill_kernel<<<eblocks, 256>>>(er, ec, ev);                         // 4
    layer_fused_kernel<64, 0><<<layer_blocks, 256, smem64>>>(W1_0, b1_0, W2_0, b2_0); // 5 (ncu)
    layer_fused_kernel<32, 1><<<layer_blocks, 256, smem32>>>(W1_1, b1_1, W2_1, b2_1); // 6
    score_kernel<<<(NB * 32) / 256, 256>>>(uids, iids, out);           // 7
}

// round 4
// speedup vs baseline: 1.4466x; 1.4466x over previous
#include <cuda_runtime.h>

// Problem constants (match reference_code)
#define NU    30000
#define NENT  70000
#define NN    100000          // NU + NENT
#define NEDGE 1600000
#define NB    4096

#define SCAN_ELEMS 512
#define NBLK_SCAN  ((NN + SCAN_ELEMS - 1) / SCAN_ELEMS)   // 196

// Scratch (device globals: allocation-free rule).
__device__ float g_feats0[NN * 64];
__device__ float g_a1[NN * 64];
__device__ float g_a2[NN * 32];
// CSR scratch
__device__ int   g_cnt[NN];
__device__ int   g_pos[NN];
__device__ int   g_rowptr[NN];       // block-local exclusive prefix
__device__ int   g_bsum[256];
__device__ int   g_boff[256];        // exclusive prefix of block sums
__device__ int2  g_ecv[NEDGE];       // x = col, y = float bits of val

// ---- f32x2 packed FMA helpers -------------------------------------------
__device__ __forceinline__ unsigned long long pack2(float lo, float hi) {
    unsigned long long r;
    asm("mov.b64 %0, {%1, %2};" : "=l"(r) : "f"(lo), "f"(hi));
    return r;
}
__device__ __forceinline__ void unpack2(unsigned long long v, float& lo, float& hi) {
    asm("mov.b64 {%0, %1}, %2;" : "=f"(lo), "=f"(hi) : "l"(v));
}
#define FMA2(d, a, b, c) \
    asm("fma.rn.f32x2 %0, %1, %2, %3;" : "=l"(d) : "l"(a), "l"(b), "l"(c))

// ---------------------------------------------------------------------------
// K0: concat a0 = [user_embed; entity_embed]  +  zero CSR counters
// ---------------------------------------------------------------------------
__global__ __launch_bounds__(256) void concat_kernel(
    const float* __restrict__ ue, const float* __restrict__ ee)
{
    int idx = blockIdx.x * 256 + threadIdx.x;           // over NN*16 float4
    if (idx < NN) { g_cnt[idx] = 0; g_pos[idx] = 0; }
    if (idx >= NN * 16) return;
    float4 v = (idx < NU * 16) ? ((const float4*)ue)[idx]
                               : ((const float4*)ee)[idx - NU * 16];
    ((float4*)g_feats0)[idx] = v;
}

// ---------------------------------------------------------------------------
// K1: histogram of rows
// ---------------------------------------------------------------------------
__global__ __launch_bounds__(256) void hist_kernel(const int* __restrict__ er)
{
    int e = blockIdx.x * 256 + threadIdx.x;
    if (e < NEDGE) atomicAdd(&g_cnt[er[e]], 1);
}

// ---------------------------------------------------------------------------
// K2: per-block exclusive scan (block-local) + block sums
// ---------------------------------------------------------------------------
__global__ __launch_bounds__(SCAN_ELEMS) void scan1_kernel()
{
    __shared__ int s[SCAN_ELEMS];
    int i = blockIdx.x * SCAN_ELEMS + threadIdx.x;
    int v = (i < NN) ? g_cnt[i] : 0;
    s[threadIdx.x] = v;
    __syncthreads();
    #pragma unroll
    for (int off = 1; off < SCAN_ELEMS; off <<= 1) {
        int t = (threadIdx.x >= off) ? s[threadIdx.x - off] : 0;
        __syncthreads();
        s[threadIdx.x] += t;
        __syncthreads();
    }
    if (i < NN) g_rowptr[i] = s[threadIdx.x] - v;        // exclusive within block
    if (threadIdx.x == SCAN_ELEMS - 1) g_bsum[blockIdx.x] = s[SCAN_ELEMS - 1];
}

// ---------------------------------------------------------------------------
// K3: scan of block sums -> g_boff
// ---------------------------------------------------------------------------
__global__ __launch_bounds__(256) void scan2_kernel()
{
    __shared__ int s[256];
    int v = (threadIdx.x < NBLK_SCAN) ? g_bsum[threadIdx.x] : 0;
    s[threadIdx.x] = v;
    __syncthreads();
    #pragma unroll
    for (int off = 1; off < 256; off <<= 1) {
        int t = (threadIdx.x >= off) ? s[threadIdx.x - off] : 0;
        __syncthreads();
        s[threadIdx.x] += t;
        __syncthreads();
    }
    g_boff[threadIdx.x] = s[threadIdx.x] - v;            // exclusive
}

// ---------------------------------------------------------------------------
// K4: fill CSR adjacency; global offset = local prefix + block offset + cursor
// ---------------------------------------------------------------------------
__global__ __launch_bounds__(256) void fill_kernel(
    const int* __restrict__ er, const int* __restrict__ ec,
    const float* __restrict__ ev)
{
    int e = blockIdx.x * 256 + threadIdx.x;
    if (e >= NEDGE) return;
    int row = er[e];
    int base = g_rowptr[row] + g_boff[row >> 9];
    int pos  = base + atomicAdd(&g_pos[row], 1);
    g_ecv[pos] = make_int2(ec[e], __float_as_int(ev[e]));
}

// ---------------------------------------------------------------------------
// Fused layer: pull-mode gather -> shared Xs/Ys (k-major, pad 65) ->
// f32x2 GEMM (j-packed) -> leaky_relu -> L2 normalize.
// Block = 64 rows, 256 threads. Gather identical to round-2 (known good).
// ---------------------------------------------------------------------------
template<int DOUT, int LAYER>
__global__ __launch_bounds__(256) void layer_fused_kernel(
    const float* __restrict__ W1, const float* __restrict__ b1,
    const float* __restrict__ W2, const float* __restrict__ b2)
{
    const float* __restrict__ feats = (LAYER == 0) ? g_feats0 : g_a1;
    float*       out                = (LAYER == 0) ? g_a1     : g_a2;

    extern __shared__ float sm[];
    float* Xs  = sm;                    // [64][65], k-major: Xs[k*65 + node]
    float* Ys  = Xs + 64 * 65;          // [64][65]
    float* W1s = Ys + 64 * 65;          // [64*DOUT] row-major [k][j]
    float* W2s = W1s + 64 * DOUT;       // [64*DOUT]
    float* Bs  = W2s + 64 * DOUT;       // [DOUT]

    const int tid  = threadIdx.x;
    const int r0   = blockIdx.x * 64;
    const int warp = tid >> 5;
    const int lane = tid & 31;

    // ---- stage W (float4) and bias sum ----
    for (int idx = tid; idx < 64 * DOUT / 4; idx += 256) {
        ((float4*)W1s)[idx] = ((const float4*)W1)[idx];
        ((float4*)W2s)[idx] = ((const float4*)W2)[idx];
    }
    if (tid < DOUT) Bs[tid] = b1[tid] + b2[tid];

    // ---- pull-mode gather: h_neigh accumulated in registers ----
    #pragma unroll 1
    for (int i = 0; i < 8; i++) {
        int rl = warp * 8 + i;
        int gr = r0 + rl;
        float f0 = 0.f, f1 = 0.f, h0 = 0.f, h1 = 0.f;
        if (gr < NN) {
            f0 = feats[gr * 64 + lane];
            f1 = feats[gr * 64 + 32 + lane];
            int beg = g_rowptr[gr] + g_boff[gr >> 9];
            int end = (gr == NN - 1) ? NEDGE
                                     : g_rowptr[gr + 1] + g_boff[(gr + 1) >> 9];
            #pragma unroll 4
            for (int e = beg; e < end; e++) {
                int2 cv = g_ecv[e];                 // same addr warp-wide
                float v = __int_as_float(cv.y);
                const float* fp = feats + (size_t)cv.x * 64;
                h0 += fp[lane] * v;
                h1 += fp[32 + lane] * v;
            }
        }
        Xs[lane * 65 + rl]        = f0 + h0;
        Xs[(lane + 32) * 65 + rl] = f1 + h1;
        Ys[lane * 65 + rl]        = f0 * h0;
        Ys[(lane + 32) * 65 + rl] = f1 * h1;
    }
    __syncthreads();

    // ---- f32x2 GEMM (j-packed): thread (tx,ty) -> 4 nodes x JT outputs ----
    constexpr int JT = DOUT / 16;       // 4 (layer0) or 2 (layer1)
    constexpr int JP = JT / 2;          // packed output pairs
    const int tx = tid & 15;
    const int ty = tid >> 4;

    unsigned long long acc[4][JP];
    #pragma unroll
    for (int i = 0; i < 4; i++)
        #pragma unroll
        for (int jp = 0; jp < JP; jp++)
            acc[i][jp] = pack2(Bs[tx * JT + 2 * jp], Bs[tx * JT + 2 * jp + 1]);

    #pragma unroll 4
    for (int k = 0; k < 64; k++) {
        unsigned long long xd[4], yd[4];
        #pragma unroll
        for (int i = 0; i < 4; i++) {
            float x = Xs[k * 65 + ty * 4 + i];
            float y = Ys[k * 65 + ty * 4 + i];
            xd[i] = pack2(x, x);
            yd[i] = pack2(y, y);
        }
        #pragma unroll
        for (int jp = 0; jp < JP; jp++) {
            unsigned long long w1 =
                *(const unsigned long long*)&W1s[k * DOUT + tx * JT + 2 * jp];
            unsigned long long w2 =
                *(const unsigned long long*)&W2s[k * DOUT + tx * JT + 2 * jp];
            #pragma unroll
            for (int i = 0; i < 4; i++) {
                FMA2(acc[i][jp], xd[i], w1, acc[i][jp]);
                FMA2(acc[i][jp], yd[i], w2, acc[i][jp]);
            }
        }
    }

    // ---- epilogue: leaky_relu + L2 normalize (half-warp reduction) ----
    #pragma unroll
    for (int i = 0; i < 4; i++) {
        float val[JT];
        float p = 0.f;
        #pragma unroll
        for (int jp = 0; jp < JP; jp++) {
            float lo, hi;
            unpack2(acc[i][jp], lo, hi);
            lo = (lo > 0.f) ? lo : 0.01f * lo;
            hi = (hi > 0.f) ? hi : 0.01f * hi;
            val[2 * jp]     = lo;
            val[2 * jp + 1] = hi;
            p += lo * lo + hi * hi;
        }
        p += __shfl_xor_sync(0xFFFFFFFFu, p, 1, 16);
        p += __shfl_xor_sync(0xFFFFFFFFu, p, 2, 16);
        p += __shfl_xor_sync(0xFFFFFFFFu, p, 4, 16);
        p += __shfl_xor_sync(0xFFFFFFFFu, p, 8, 16);
        float inv = 1.f / fmaxf(sqrtf(p), 1e-12f);
        int gr = r0 + ty * 4 + i;
        if (gr < NN) {
            if constexpr (JT == 4) {
                float4 o = make_float4(val[0] * inv, val[1] * inv,
                                       val[2] * inv, val[3] * inv);
                ((float4*)out)[gr * (DOUT / 4) + tx] = o;
            } else {
                float2 o = make_float2(val[0] * inv, val[1] * inv);
                ((float2*)out)[gr * (DOUT / 2) + tx] = o;
            }
        }
    }
}

// ---------------------------------------------------------------------------
// Scoring — warp per pair, dot over concat(a0[64], a1[64], a2[32]).
// ---------------------------------------------------------------------------
__global__ __launch_bounds__(256) void score_kernel(
    const int* __restrict__ uids, const int* __restrict__ iids,
    float* __restrict__ out)
{
    int w = (blockIdx.x * 256 + threadIdx.x) >> 5;
    int l = threadIdx.x & 31;
    if (w >= NB) return;
    int u  = uids[w];
    int it = NU + iids[w];

    const float* fu = g_feats0 + u  * 64;
    const float* fi = g_feats0 + it * 64;
    float s = fu[l] * fi[l] + fu[l + 32] * fi[l + 32];
    const float* au = g_a1 + u  * 64;
    const float* ai = g_a1 + it * 64;
    s += au[l] * ai[l] + au[l + 32] * ai[l + 32];
    s += g_a2[u * 32 + l] * g_a2[it * 32 + l];

    s += __shfl_xor_sync(0xFFFFFFFFu, s, 16);
    s += __shfl_xor_sync(0xFFFFFFFFu, s, 8);
    s += __shfl_xor_sync(0xFFFFFFFFu, s, 4);
    s += __shfl_xor_sync(0xFFFFFFFFu, s, 2);
    s += __shfl_xor_sync(0xFFFFFFFFu, s, 1);
    if (l == 0) out[w] = s;
}

// ---------------------------------------------------------------------------
extern "C" void kernel_launch(void* const* d_in, const int* in_sizes, int n_in,
                              void* d_out, int out_size)
{
    const int*   er   = (const int*)  d_in[0];
    const int*   ec   = (const int*)  d_in[1];
    const float* ev   = (const float*)d_in[2];
    const float* ue   = (const float*)d_in[3];
    const float* ee   = (const float*)d_in[4];
    const float* W1_0 = (const float*)d_in[5];
    const float* b1_0 = (const float*)d_in[6];
    const float* W2_0 = (const float*)d_in[7];
    const float* b2_0 = (const float*)d_in[8];
    const float* W1_1 = (const float*)d_in[9];
    const float* b1_1 = (const float*)d_in[10];
    const float* W2_1 = (const float*)d_in[11];
    const float* b2_1 = (const float*)d_in[12];
    const int*   uids = (const int*)  d_in[13];
    const int*   iids = (const int*)  d_in[14];
    float*       out  = (float*)d_out;

    const size_t smem64 = (size_t)(64 * 65 * 2 + 64 * 64 * 2 + 64) * sizeof(float); // 66560 B
    const size_t smem32 = (size_t)(64 * 65 * 2 + 64 * 32 * 2 + 32) * sizeof(float); // 49792 B
    cudaFuncSetAttribute(layer_fused_kernel<64, 0>,
                         cudaFuncAttributeMaxDynamicSharedMemorySize, (int)smem64);
    cudaFuncSetAttribute(layer_fused_kernel<32, 1>,
                         cudaFuncAttributeMaxDynamicSharedMemorySize, (int)smem32);

    const int layer_blocks = (NN + 63) / 64;
    const int eblocks = (NEDGE + 255) / 256;

    concat_kernel<<<(NN * 16 + 255) / 256, 256>>>(ue, ee);             // 0
    hist_kernel<<<eblocks, 256>>>(er);                                 // 1
    scan1_kernel<<<NBLK_SCAN, SCAN_ELEMS>>>();                         // 2
    scan2_kernel<<<1, 256>>>();                                        // 3
    fill_kernel<<<eblocks, 256>>>(er, ec, ev);                         // 4
    layer_fused_kernel<64, 0><<<layer_blocks, 256, smem64>>>(W1_0, b1_0, W2_0, b2_0); // 5 (ncu)
    layer_fused_kernel<32, 1><<<layer_blocks, 256, smem32>>>(W1_1, b1_1, W2_1, b2_1); // 6
    score_kernel<<<(NB * 32) / 256, 256>>>(uids, iids, out);           // 7
}